// round 2
// baseline (speedup 1.0000x reference)
#include <cuda_runtime.h>
#include <math.h>

// Problem constants
#define B_SZ    2048
#define HDIM    1024
#define DDIM    512
#define MAXN    64
#define MID_SP  512
#define MID_CD  512
#define MID_DEC 768

// Scratch (device globals; no allocation allowed)
__device__ int   g_n[B_SZ];
__device__ float g_enc[65 * HDIM];
__device__ float g_zc[B_SZ * HDIM];

__device__ __forceinline__ float mishf(float x) {
    float sp = log1pf(expf(x));
    if (x > 20.f) sp = x;                 // overflow guard
    return x * tanhf(sp);
}

// ---------------- packed f32x2 helpers (sm_103a FFMA2) ----------------
__device__ __forceinline__ unsigned long long dup2(float x) {
    unsigned long long r;
    asm("mov.b64 %0, {%1, %1};" : "=l"(r) : "f"(x));
    return r;
}
__device__ __forceinline__ void fma2(unsigned long long& d,
                                     unsigned long long a,
                                     unsigned long long b) {
    asm("fma.rn.f32x2 %0, %1, %2, %0;" : "+l"(d) : "l"(a), "l"(b));
}
__device__ __forceinline__ float2 unpack2(unsigned long long v) {
    float2 f;
    asm("mov.b64 {%0, %1}, %2;" : "=f"(f.x), "=f"(f.y) : "l"(v));
    return f;
}

// =====================================================================
// Kernel 1: size_pred MLP -> g_n[b]
//   h = mish(LN(z @ sp_w1 + sp_b1, g, beta));  n = clip(rint(h@sp_w2+b2),0,64)
// grid 256 blocks x 256 thr, 8 batch rows per block
// =====================================================================
__global__ __launch_bounds__(256)
void size_pred_kernel(const float* __restrict__ z,
                      const float* __restrict__ w1,   // [1024,512]
                      const float* __restrict__ b1v,
                      const float* __restrict__ g,
                      const float* __restrict__ beta,
                      const float* __restrict__ w2,   // [512,1]
                      const float* __restrict__ b2v)
{
    __shared__ float z_s[8][HDIM];
    __shared__ float red1[256], red2[256];
    __shared__ float mu_s[8], rs_s[8];

    const int tid = threadIdx.x;
    const int b0  = blockIdx.x * 8;

    for (int i = tid; i < 8 * HDIM; i += 256)
        z_s[i >> 10][i & 1023] = z[(size_t)b0 * HDIM + i];
    __syncthreads();

    float pre[8][2];
#pragma unroll
    for (int r = 0; r < 8; r++) { pre[r][0] = 0.f; pre[r][1] = 0.f; }

    for (int k = 0; k < HDIM; k++) {
        float wa = w1[k * MID_SP + tid];
        float wb = w1[k * MID_SP + tid + 256];
#pragma unroll
        for (int r = 0; r < 8; r++) {
            float zv = z_s[r][k];
            pre[r][0] = fmaf(zv, wa, pre[r][0]);
            pre[r][1] = fmaf(zv, wb, pre[r][1]);
        }
    }
    float ba = b1v[tid], bb = b1v[tid + 256];
#pragma unroll
    for (int r = 0; r < 8; r++) { pre[r][0] += ba; pre[r][1] += bb; }

    // LayerNorm statistics per row (512 elems)
    for (int r = 0; r < 8; r++) {
        red1[tid] = pre[r][0] + pre[r][1];
        red2[tid] = pre[r][0] * pre[r][0] + pre[r][1] * pre[r][1];
        __syncthreads();
        for (int s = 128; s > 0; s >>= 1) {
            if (tid < s) { red1[tid] += red1[tid + s]; red2[tid] += red2[tid + s]; }
            __syncthreads();
        }
        if (tid == 0) {
            float mu  = red1[0] * (1.f / 512.f);
            float var = red2[0] * (1.f / 512.f) - mu * mu;
            mu_s[r] = mu;
            rs_s[r] = rsqrtf(var + 1e-5f);
        }
        __syncthreads();
    }

    float ga = g[tid], gb = g[tid + 256];
    float bta = beta[tid], btb = beta[tid + 256];
    float w2a = w2[tid], w2b = w2[tid + 256];

    for (int r = 0; r < 8; r++) {
        float h0 = mishf((pre[r][0] - mu_s[r]) * rs_s[r] * ga + bta);
        float h1 = mishf((pre[r][1] - mu_s[r]) * rs_s[r] * gb + btb);
        red1[tid] = h0 * w2a + h1 * w2b;
        __syncthreads();
        for (int s = 128; s > 0; s >>= 1) {
            if (tid < s) red1[tid] += red1[tid + s];
            __syncthreads();
        }
        if (tid == 0) {
            float logit = red1[0] + b2v[0];
            int n = (int)rintf(logit);      // round-half-even, matches jnp.round
            n = min(max(n, 0), MAXN);
            g_n[b0 + r] = n;
        }
        __syncthreads();
    }
}

// =====================================================================
// Kernel 2: cardinality table for all 65 possible n values
//   g_enc[v,:] = mish(v*cd_w1 + cd_b1) @ cd_w2 + cd_b2
// =====================================================================
__global__ __launch_bounds__(256)
void enc_kernel(const float* __restrict__ cw1, const float* __restrict__ cb1,
                const float* __restrict__ cw2, const float* __restrict__ cb2)
{
    __shared__ float m_s[MID_CD];
    const int v = blockIdx.x;           // 0..64
    const int tid = threadIdx.x;

    for (int j = tid; j < MID_CD; j += 256)
        m_s[j] = mishf((float)v * cw1[j] + cb1[j]);
    __syncthreads();

    for (int j = tid; j < HDIM; j += 256) {
        float acc = cb2[j];
        for (int m = 0; m < MID_CD; m++)
            acc = fmaf(m_s[m], cw2[m * HDIM + j], acc);
        g_enc[v * HDIM + j] = acc;
    }
}

// =====================================================================
// Kernel 3: zc = z - enc_table[n[b]]
// =====================================================================
__global__ __launch_bounds__(256)
void zc_kernel(const float* __restrict__ z)
{
    int idx = blockIdx.x * 256 + threadIdx.x;   // 2048*1024 total
    int b = idx >> 10, i = idx & 1023;
    g_zc[idx] = z[idx] - g_enc[g_n[b] * HDIM + i];
}

// =====================================================================
// Kernel 4: fused decoder.
//   Per block: 16 rows (fixed batch b, k0..k0+15).
//   Phase 1: t[16,768] = mish( (zc[b] (*) key[k]) @ W1 + b1 )   (A in smem)
//   Phase 2: out[16,512] = t @ W2 + b2, masked write
// 256 threads. Dynamic smem ~176KB.
// =====================================================================
#define AST 20   // padded row stride (floats) for a_s/t_s, 16B-aligned float4 at r0=4*ty

__global__ __launch_bounds__(256)
void decoder_kernel(const float* __restrict__ key,
                    const float* __restrict__ W1, const float* __restrict__ b1,
                    const float* __restrict__ W2, const float* __restrict__ b2,
                    float* __restrict__ out)
{
    const int blk = blockIdx.x;        // 8192 = 2048 batches * 4 row-tiles
    const int b   = blk >> 2;
    const int k0  = (blk & 3) * 16;
    const int n   = g_n[b];
    const int tid = threadIdx.x;

    float* outrow = out + ((size_t)b * MAXN + k0) * DDIM;

    if (k0 >= n) {   // whole tile masked: zero-fill and exit (uniform branch)
        float4 zf = make_float4(0.f, 0.f, 0.f, 0.f);
        float4* o4 = (float4*)outrow;
        for (int i = tid; i < 16 * DDIM / 4; i += 256) o4[i] = zf;
        return;
    }

    extern __shared__ float smem[];
    float* zc_s = smem;                       // 1024
    float* a_s  = zc_s + HDIM;                // 1024 * 20
    float* t_s  = a_s  + HDIM * AST;          // 768 * 20
    float* w_s  = t_s  + MID_DEC * AST;       // 32 * 256

    // stage zc row
    for (int i = tid; i < HDIM; i += 256) zc_s[i] = g_zc[(size_t)b * HDIM + i];
    __syncthreads();

    // stage A^T: a_s[k][r] = zc[k] * key[k0+r][k]
    for (int r = 0; r < 16; r++) {
        const float* kr = key + (size_t)(k0 + r) * HDIM;
        for (int k = tid; k < HDIM; k += 256)
            a_s[k * AST + r] = zc_s[k] * kr[k];
    }
    __syncthreads();

    const int tx = tid & 63;           // 64 col-groups
    const int ty = tid >> 6;           // 4 row-groups
    const int r0 = ty * 4;
    const int c4 = tx * 4;

    // ---------------- Phase 1: 768 output cols in 3 tiles of 256 ----------------
    for (int ct = 0; ct < 3; ct++) {
        const int cbase = ct * 256;
        unsigned long long acc2[4][2];
#pragma unroll
        for (int i = 0; i < 4; i++) { acc2[i][0] = 0ull; acc2[i][1] = 0ull; }

        for (int kk = 0; kk < HDIM; kk += 32) {
            // stage W1 tile [32][256]
#pragma unroll
            for (int i = 0; i < 8; i++) {
                int e   = tid + i * 256;
                int row = e >> 6;
                int col = (e & 63) * 4;
                *(float4*)&w_s[row * 256 + col] =
                    *(const float4*)&W1[(size_t)(kk + row) * MID_DEC + cbase + col];
            }
            __syncthreads();
#pragma unroll
            for (int k = 0; k < 32; k++) {
                float4 av = *(const float4*)&a_s[(kk + k) * AST + r0];   // broadcast
                ulonglong2 wv = *(const ulonglong2*)&w_s[k * 256 + c4];
                unsigned long long a0 = dup2(av.x), a1 = dup2(av.y);
                unsigned long long a2 = dup2(av.z), a3 = dup2(av.w);
                fma2(acc2[0][0], a0, wv.x); fma2(acc2[0][1], a0, wv.y);
                fma2(acc2[1][0], a1, wv.x); fma2(acc2[1][1], a1, wv.y);
                fma2(acc2[2][0], a2, wv.x); fma2(acc2[2][1], a2, wv.y);
                fma2(acc2[3][0], a3, wv.x); fma2(acc2[3][1], a3, wv.y);
            }
            __syncthreads();
        }
        // epilogue: +bias, mish, store transposed into t_s
        float accf[4][4];
#pragma unroll
        for (int i = 0; i < 4; i++) {
            float2 u0 = unpack2(acc2[i][0]);
            float2 u1 = unpack2(acc2[i][1]);
            accf[i][0] = u0.x; accf[i][1] = u0.y; accf[i][2] = u1.x; accf[i][3] = u1.y;
        }
#pragma unroll
        for (int j = 0; j < 4; j++) {
            int col = cbase + c4 + j;
            float bb = b1[col];
            float4 v;
            v.x = mishf(accf[0][j] + bb);
            v.y = mishf(accf[1][j] + bb);
            v.z = mishf(accf[2][j] + bb);
            v.w = mishf(accf[3][j] + bb);
            *(float4*)&t_s[col * AST + r0] = v;
        }
    }
    __syncthreads();

    // ---------------- Phase 2: 512 output cols in 2 tiles of 256 ----------------
    for (int ct = 0; ct < 2; ct++) {
        const int cbase = ct * 256;
        unsigned long long acc2[4][2];
#pragma unroll
        for (int i = 0; i < 4; i++) { acc2[i][0] = 0ull; acc2[i][1] = 0ull; }

        for (int kk = 0; kk < MID_DEC; kk += 32) {
#pragma unroll
            for (int i = 0; i < 8; i++) {
                int e   = tid + i * 256;
                int row = e >> 6;
                int col = (e & 63) * 4;
                *(float4*)&w_s[row * 256 + col] =
                    *(const float4*)&W2[(size_t)(kk + row) * DDIM + cbase + col];
            }
            __syncthreads();
#pragma unroll
            for (int k = 0; k < 32; k++) {
                float4 av = *(const float4*)&t_s[(kk + k) * AST + r0];
                ulonglong2 wv = *(const ulonglong2*)&w_s[k * 256 + c4];
                unsigned long long a0 = dup2(av.x), a1 = dup2(av.y);
                unsigned long long a2 = dup2(av.z), a3 = dup2(av.w);
                fma2(acc2[0][0], a0, wv.x); fma2(acc2[0][1], a0, wv.y);
                fma2(acc2[1][0], a1, wv.x); fma2(acc2[1][1], a1, wv.y);
                fma2(acc2[2][0], a2, wv.x); fma2(acc2[2][1], a2, wv.y);
                fma2(acc2[3][0], a3, wv.x); fma2(acc2[3][1], a3, wv.y);
            }
            __syncthreads();
        }
        float accf[4][4];
#pragma unroll
        for (int i = 0; i < 4; i++) {
            float2 u0 = unpack2(acc2[i][0]);
            float2 u1 = unpack2(acc2[i][1]);
            accf[i][0] = u0.x; accf[i][1] = u0.y; accf[i][2] = u1.x; accf[i][3] = u1.y;
        }
#pragma unroll
        for (int i = 0; i < 4; i++) {
            int r = r0 + i;
            bool valid = (k0 + r) < n;
            int col = cbase + c4;
            float4 v;
            v.x = valid ? accf[i][0] + b2[col + 0] : 0.f;
            v.y = valid ? accf[i][1] + b2[col + 1] : 0.f;
            v.z = valid ? accf[i][2] + b2[col + 2] : 0.f;
            v.w = valid ? accf[i][3] + b2[col + 3] : 0.f;
            *(float4*)&outrow[(size_t)r * DDIM + col] = v;
        }
    }
}

// =====================================================================
// Kernel 5: batch indices output (float), appended after x if room
// =====================================================================
__global__ __launch_bounds__(256)
void batch_kernel(float* __restrict__ outb)
{
    int idx = blockIdx.x * 256 + threadIdx.x;   // 131072
    int b = idx >> 6, k = idx & 63;
    outb[idx] = (k < g_n[b]) ? (float)b : -1.0f;
}

// =====================================================================
extern "C" void kernel_launch(void* const* d_in, const int* in_sizes, int n_in,
                              void* d_out, int out_size)
{
    const float* z      = (const float*)d_in[0];
    const float* key    = (const float*)d_in[1];
    const float* sp_w1  = (const float*)d_in[2];
    const float* sp_b1  = (const float*)d_in[3];
    const float* sp_g   = (const float*)d_in[4];
    const float* sp_bt  = (const float*)d_in[5];
    const float* sp_w2  = (const float*)d_in[6];
    const float* sp_b2  = (const float*)d_in[7];
    const float* cd_w1  = (const float*)d_in[8];
    const float* cd_b1  = (const float*)d_in[9];
    const float* cd_w2  = (const float*)d_in[10];
    const float* cd_b2  = (const float*)d_in[11];
    const float* dec_w1 = (const float*)d_in[12];
    const float* dec_b1 = (const float*)d_in[13];
    const float* dec_w2 = (const float*)d_in[14];
    const float* dec_b2 = (const float*)d_in[15];
    float* out = (float*)d_out;

    const int SMEM_BYTES = (HDIM + HDIM * AST + MID_DEC * AST + 32 * 256) * sizeof(float);
    cudaFuncSetAttribute(decoder_kernel,
                         cudaFuncAttributeMaxDynamicSharedMemorySize, SMEM_BYTES);

    size_pred_kernel<<<B_SZ / 8, 256>>>(z, sp_w1, sp_b1, sp_g, sp_bt, sp_w2, sp_b2);
    enc_kernel<<<65, 256>>>(cd_w1, cd_b1, cd_w2, cd_b2);
    zc_kernel<<<(B_SZ * HDIM) / 256, 256>>>(z);
    decoder_kernel<<<B_SZ * 4, 256, SMEM_BYTES>>>(key, dec_w1, dec_b1, dec_w2, dec_b2, out);

    long long x_elems = (long long)B_SZ * MAXN * DDIM;   // 67,108,864
    if ((long long)out_size >= x_elems + (long long)B_SZ * MAXN)
        batch_kernel<<<(B_SZ * MAXN) / 256, 256>>>(out + x_elems);
}

// round 4
// speedup vs baseline: 4.3633x; 4.3633x over previous
#include <cuda_runtime.h>
#include <math.h>
#include <stdint.h>

#define B_SZ 2048
#define HDIM 1024
#define DDIM 512
#define MAXN 64
#define MID_SP 512
#define MID_CD 512
#define MID_DEC 768
#define NROWS (B_SZ * MAXN)

__device__ int   g_n[B_SZ];
__device__ int   g_off[B_SZ];
__device__ int   g_vpad;
__device__ int   g_rowmap[NROWS];
__device__ float g_enc[65 * HDIM];
__device__ float g_zc[B_SZ * HDIM];
__device__ float g_W1T[MID_DEC * HDIM];
__device__ float g_W2T[DDIM * MID_DEC];
__device__ float g_T[(size_t)NROWS * MID_DEC];

__device__ __forceinline__ float mishf(float x) {
    float sp = log1pf(expf(x));
    if (x > 20.f) sp = x;
    return x * tanhf(sp);
}
// FMA-only mish (no MUFU): exp = 2^n * poly6, rcp = magic + 3 Newton.
__device__ __forceinline__ float mish_poly(float x) {
    float xc = fminf(fmaxf(x, -30.f), 20.f);
    float t = xc * 1.44269504089f;
    float fn = rintf(t);
    float g = (t - fn) * 0.69314718056f;
    float p = 1.f / 720.f;
    p = fmaf(p, g, 1.f / 120.f);
    p = fmaf(p, g, 1.f / 24.f);
    p = fmaf(p, g, 1.f / 6.f);
    p = fmaf(p, g, 0.5f);
    p = fmaf(p, g, 1.f);
    p = fmaf(p, g, 1.f);
    float ex = p * __uint_as_float(((unsigned)((int)fn + 127)) << 23);
    float u = 1.f + ex;
    float d = fmaf(u, u, 1.f);
    float r = __uint_as_float(0x7EF311C3u - __float_as_uint(d));
    r = r * (2.f - d * r);
    r = r * (2.f - d * r);
    r = r * (2.f - d * r);
    float m = x * (fmaf(u, u, -1.f) * r);
    return (x > 20.f) ? x : m;
}
__device__ __forceinline__ float tf32r(float x) {
    unsigned r;
    asm("cvt.rna.tf32.f32 %0, %1;" : "=r"(r) : "f"(x));
    return __uint_as_float(r);
}
__device__ __forceinline__ void mma_tf32(float* d, const uint32_t* a, const uint32_t* b) {
    asm volatile(
        "mma.sync.aligned.m16n8k8.row.col.f32.tf32.tf32.f32 "
        "{%0,%1,%2,%3}, {%4,%5,%6,%7}, {%8,%9}, {%0,%1,%2,%3};"
        : "+f"(d[0]), "+f"(d[1]), "+f"(d[2]), "+f"(d[3])
        : "r"(a[0]), "r"(a[1]), "r"(a[2]), "r"(a[3]), "r"(b[0]), "r"(b[1]));
}
#define CPASYNC16(dst, src) \
    asm volatile("cp.async.cg.shared.global [%0], [%1], 16;" :: "r"(dst), "l"(src))
#define CPCOMMIT() asm volatile("cp.async.commit_group;" ::: "memory")
#define CPWAIT0()  asm volatile("cp.async.wait_group 0;" ::: "memory")
#define CPWAIT1()  asm volatile("cp.async.wait_group 1;" ::: "memory")

__device__ __forceinline__ uint32_t smem_u32(const void* p) {
    uint32_t a;
    asm("{ .reg .u64 t; cvta.to.shared.u64 t, %1; cvt.u32.u64 %0, t; }" : "=r"(a) : "l"(p));
    return a;
}

// ---------------- size_pred ----------------
__global__ __launch_bounds__(256)
void size_pred_kernel(const float* __restrict__ z, const float* __restrict__ w1,
                      const float* __restrict__ b1v, const float* __restrict__ g,
                      const float* __restrict__ beta, const float* __restrict__ w2,
                      const float* __restrict__ b2v)
{
    __shared__ float z_s[8][HDIM];
    __shared__ float red1[256], red2[256];
    __shared__ float mu_s[8], rs_s[8];
    const int tid = threadIdx.x, b0 = blockIdx.x * 8;
    for (int i = tid; i < 8 * HDIM; i += 256)
        z_s[i >> 10][i & 1023] = z[(size_t)b0 * HDIM + i];
    __syncthreads();
    float pre[8][2];
#pragma unroll
    for (int r = 0; r < 8; r++) { pre[r][0] = 0.f; pre[r][1] = 0.f; }
    for (int k = 0; k < HDIM; k++) {
        float wa = w1[k * MID_SP + tid], wb = w1[k * MID_SP + tid + 256];
#pragma unroll
        for (int r = 0; r < 8; r++) {
            float zv = z_s[r][k];
            pre[r][0] = fmaf(zv, wa, pre[r][0]);
            pre[r][1] = fmaf(zv, wb, pre[r][1]);
        }
    }
    float ba = b1v[tid], bb = b1v[tid + 256];
#pragma unroll
    for (int r = 0; r < 8; r++) { pre[r][0] += ba; pre[r][1] += bb; }
    for (int r = 0; r < 8; r++) {
        red1[tid] = pre[r][0] + pre[r][1];
        red2[tid] = pre[r][0] * pre[r][0] + pre[r][1] * pre[r][1];
        __syncthreads();
        for (int s = 128; s > 0; s >>= 1) {
            if (tid < s) { red1[tid] += red1[tid + s]; red2[tid] += red2[tid + s]; }
            __syncthreads();
        }
        if (tid == 0) {
            float mu = red1[0] * (1.f / 512.f);
            float var = red2[0] * (1.f / 512.f) - mu * mu;
            mu_s[r] = mu; rs_s[r] = rsqrtf(var + 1e-5f);
        }
        __syncthreads();
    }
    float ga = g[tid], gb = g[tid + 256], bta = beta[tid], btb = beta[tid + 256];
    float w2a = w2[tid], w2b = w2[tid + 256];
    for (int r = 0; r < 8; r++) {
        float h0 = mishf((pre[r][0] - mu_s[r]) * rs_s[r] * ga + bta);
        float h1 = mishf((pre[r][1] - mu_s[r]) * rs_s[r] * gb + btb);
        red1[tid] = h0 * w2a + h1 * w2b;
        __syncthreads();
        for (int s = 128; s > 0; s >>= 1) {
            if (tid < s) red1[tid] += red1[tid + s];
            __syncthreads();
        }
        if (tid == 0) {
            int n = (int)rintf(red1[0] + b2v[0]);
            g_n[b0 + r] = min(max(n, 0), MAXN);
        }
        __syncthreads();
    }
}

// ---------------- cardinality table ----------------
__global__ __launch_bounds__(256)
void enc_kernel(const float* __restrict__ cw1, const float* __restrict__ cb1,
                const float* __restrict__ cw2, const float* __restrict__ cb2)
{
    __shared__ float m_s[MID_CD];
    const int v = blockIdx.x, tid = threadIdx.x;
    for (int j = tid; j < MID_CD; j += 256)
        m_s[j] = mishf((float)v * cw1[j] + cb1[j]);
    __syncthreads();
    for (int j = tid; j < HDIM; j += 256) {
        float acc = cb2[j];
        for (int m = 0; m < MID_CD; m++)
            acc = fmaf(m_s[m], cw2[m * HDIM + j], acc);
        g_enc[v * HDIM + j] = acc;
    }
}

__global__ __launch_bounds__(256)
void zc_kernel(const float* __restrict__ z)
{
    int idx = blockIdx.x * 256 + threadIdx.x;
    int b = idx >> 10, i = idx & 1023;
    g_zc[idx] = z[idx] - g_enc[g_n[b] * HDIM + i];
}

// transpose + tf32 round: src[R][C] -> dst[C][R]; which: 0->W1T, 1->W2T
__global__ void transpose_tf32(const float* __restrict__ src, int R, int C, int which)
{
    __shared__ float t[32][33];
    float* dst = which ? g_W2T : g_W1T;
    int c0 = blockIdx.x * 32, r0 = blockIdx.y * 32;
#pragma unroll
    for (int i = 0; i < 32; i += 8)
        t[threadIdx.y + i][threadIdx.x] = src[(size_t)(r0 + threadIdx.y + i) * C + c0 + threadIdx.x];
    __syncthreads();
#pragma unroll
    for (int i = 0; i < 32; i += 8)
        dst[(size_t)(c0 + threadIdx.y + i) * R + r0 + threadIdx.x] = tf32r(t[threadIdx.x][threadIdx.y + i]);
}

__global__ __launch_bounds__(1024)
void scan_kernel()
{
    __shared__ int s[2048];
    int t = threadIdx.x;
    s[t] = g_n[t]; s[t + 1024] = g_n[t + 1024];
    __syncthreads();
    for (int off = 1; off < 2048; off <<= 1) {
        int a = (t >= off) ? s[t - off] : 0;
        int b = s[t + 1024 - off];
        __syncthreads();
        s[t] += a; s[t + 1024] += b;
        __syncthreads();
    }
    g_off[t] = s[t] - g_n[t];
    g_off[t + 1024] = s[t + 1024] - g_n[t + 1024];
    if (t == 1023) g_vpad = (s[2047] + 127) & ~127;
}

__global__ void rminit_kernel() { g_rowmap[blockIdx.x * 256 + threadIdx.x] = -1; }
__global__ void rmfill_kernel() {
    int b = blockIdx.x, k = threadIdx.x;
    if (k < g_n[b]) g_rowmap[g_off[b] + k] = (b << 6) | k;
}

__global__ __launch_bounds__(128)
void outfill_kernel(float* __restrict__ out, float* __restrict__ outb)
{
    int r = blockIdx.x;
    int b = r >> 6, k = r & 63;
    int n = g_n[b];
    if (outb && threadIdx.x == 0) outb[r] = (k < n) ? (float)b : -1.0f;
    if (k >= n)
        ((float4*)(out + (size_t)r * DDIM))[threadIdx.x] = make_float4(0.f, 0.f, 0.f, 0.f);
}

// =====================================================================
// GEMM1: g_T[tile rows, 768] = tf32(mish( (zc*key) @ W1 + b1 ))
// CTA 128m x 256n, 512 thr (16 warps, warp 32x64), K=1024, chunk 32.
// smem: rm[128] | As[128][36] | Bs[2][256][36]
// =====================================================================
#define PAD 36
#define G1_RM   0
#define G1_AS   128
#define G1_BS0  (G1_AS + 128 * PAD)
#define G1_BS1  (G1_BS0 + 256 * PAD)
#define G1_FLTS (G1_BS1 + 256 * PAD)

__global__ void __launch_bounds__(512, 1)
gemm1_kernel(const float* __restrict__ key, const float* __restrict__ b1)
{
    const int tile = blockIdx.x;
    if (tile * 128 >= g_vpad) return;
    extern __shared__ float sm[];
    int* rm_s = (int*)sm;
    float* As = sm + G1_AS;
    float* Bs[2] = { sm + G1_BS0, sm + G1_BS1 };
    const uint32_t sb = smem_u32(sm);

    const int tid = threadIdx.x, lane = tid & 31, wid = tid >> 5;
    const int mw = wid & 3, nw = wid >> 2;          // 4 m-warps x 4 n-warps
    const int nc0 = blockIdx.y * 256;               // 0,256,512

    if (tid < 128) rm_s[tid] = g_rowmap[tile * 128 + tid];
    __syncthreads();

    // A staging map: 2 x (row, seg) per thread
    const float* zp[2]; const float* kp[2]; int sts[2];
#pragma unroll
    for (int i = 0; i < 2; i++) {
        int idx = tid + i * 512;
        int r = idx >> 3, seg = idx & 7;
        int rm = rm_s[r]; if (rm < 0) rm = 0;
        zp[i] = g_zc + (size_t)(rm >> 6) * HDIM + seg * 4;
        kp[i] = key + (size_t)(rm & 63) * HDIM + seg * 4;
        sts[i] = G1_AS + r * PAD + seg * 4;
    }
    // B staging map: 4 x (row, seg)
    size_t bsrc[4]; int bdst[4];
#pragma unroll
    for (int i = 0; i < 4; i++) {
        int idx = tid + i * 512;
        int r = idx >> 3, seg = idx & 7;
        bsrc[i] = (size_t)(nc0 + r) * HDIM + seg * 4;
        bdst[i] = r * PAD + seg * 4;
    }

    float4 za[2], ka[2];
#pragma unroll
    for (int i = 0; i < 2; i++) { za[i] = *(const float4*)zp[i]; ka[i] = *(const float4*)kp[i]; }
#pragma unroll
    for (int i = 0; i < 4; i++)
        CPASYNC16(sb + (uint32_t)(G1_BS0 + bdst[i]) * 4, (const char*)(g_W1T + bsrc[i]));
    CPCOMMIT();

    float acc[2][8][4];
#pragma unroll
    for (int mt = 0; mt < 2; mt++)
#pragma unroll
        for (int nt = 0; nt < 8; nt++)
#pragma unroll
            for (int q = 0; q < 4; q++) acc[mt][nt][q] = 0.f;

    const int arow0 = mw * 32 + (lane >> 2);
    const int brow0 = nw * 64 + (lane >> 2);
    const int kq = lane & 3;
    const uint32_t* smu = (const uint32_t*)sm;

    for (int kt = 0; kt < 32; kt++) {
        const int buf = kt & 1;
        // store A chunk kt (regs already loaded)
#pragma unroll
        for (int i = 0; i < 2; i++) {
            float4 a;
            a.x = tf32r(za[i].x * ka[i].x); a.y = tf32r(za[i].y * ka[i].y);
            a.z = tf32r(za[i].z * ka[i].z); a.w = tf32r(za[i].w * ka[i].w);
            *(float4*)(sm + sts[i]) = a;
        }
        if (kt + 1 < 32) {
#pragma unroll
            for (int i = 0; i < 2; i++) {
                za[i] = *(const float4*)(zp[i] + (kt + 1) * 32);
                ka[i] = *(const float4*)(kp[i] + (kt + 1) * 32);
            }
            const int nb = (kt + 1) & 1;
#pragma unroll
            for (int i = 0; i < 4; i++)
                CPASYNC16(sb + (uint32_t)((nb ? G1_BS1 : G1_BS0) + bdst[i]) * 4,
                          (const char*)(g_W1T + bsrc[i] + (kt + 1) * 32));
            CPCOMMIT();
            CPWAIT1();
        } else {
            CPWAIT0();
        }
        __syncthreads();

        const uint32_t* Bu = (const uint32_t*)Bs[buf];
#pragma unroll
        for (int ks = 0; ks < 4; ks++) {
            const int kb = ks * 8;
            uint32_t af[2][4];
#pragma unroll
            for (int mt = 0; mt < 2; mt++) {
                int ro = (arow0 + mt * 16) * PAD + kb + kq;
                af[mt][0] = smu[G1_AS + ro];
                af[mt][1] = smu[G1_AS + ro + 8 * PAD];
                af[mt][2] = smu[G1_AS + ro + 4];
                af[mt][3] = smu[G1_AS + ro + 8 * PAD + 4];
            }
#pragma unroll
            for (int nt = 0; nt < 8; nt++) {
                uint32_t bf[2];
                int bo = (brow0 + nt * 8) * PAD + kb + kq;
                bf[0] = Bu[bo];
                bf[1] = Bu[bo + 4];
                mma_tf32(acc[0][nt], af[0], bf);
                mma_tf32(acc[1][nt], af[1], bf);
            }
        }
        __syncthreads();
    }

    // epilogue: +bias, mish, tf32 round -> g_T
    const int col00 = nc0 + nw * 64 + 2 * (lane & 3);
    const int row00 = tile * 128 + mw * 32 + (lane >> 2);
#pragma unroll
    for (int mt = 0; mt < 2; mt++) {
#pragma unroll
        for (int nt = 0; nt < 8; nt++) {
            int col = col00 + nt * 8;
            float2 bb = *(const float2*)(b1 + col);
            float* p0 = g_T + (size_t)(row00 + mt * 16) * MID_DEC + col;
            float* p1 = p0 + 8 * MID_DEC;
            float2 v0, v1;
            v0.x = tf32r(mish_poly(acc[mt][nt][0] + bb.x));
            v0.y = tf32r(mish_poly(acc[mt][nt][1] + bb.y));
            v1.x = tf32r(mish_poly(acc[mt][nt][2] + bb.x));
            v1.y = tf32r(mish_poly(acc[mt][nt][3] + bb.y));
            *(float2*)p0 = v0;
            *(float2*)p1 = v1;
        }
    }
}

// =====================================================================
// GEMM2: out[rowmap rows, 512] = g_T @ W2 + b2 (scatter)
// smem: rm[128] | As[2][128][36] | Bs[2][256][36]
// =====================================================================
#define G2_RM   0
#define G2_AS0  128
#define G2_AS1  (G2_AS0 + 128 * PAD)
#define G2_BS0  (G2_AS1 + 128 * PAD)
#define G2_BS1  (G2_BS0 + 256 * PAD)
#define G2_FLTS (G2_BS1 + 256 * PAD)

__global__ void __launch_bounds__(512, 1)
gemm2_kernel(const float* __restrict__ b2, float* __restrict__ out)
{
    const int tile = blockIdx.x;
    if (tile * 128 >= g_vpad) return;
    extern __shared__ float sm[];
    int* rm_s = (int*)sm;
    const uint32_t sb = smem_u32(sm);

    const int tid = threadIdx.x, lane = tid & 31, wid = tid >> 5;
    const int mw = wid & 3, nw = wid >> 2;
    const int nc0 = blockIdx.y * 256;   // 0,256

    if (tid < 128) rm_s[tid] = g_rowmap[tile * 128 + tid];

    // staging maps
    size_t asrc[2]; int adst[2];
#pragma unroll
    for (int i = 0; i < 2; i++) {
        int idx = tid + i * 512;
        int r = idx >> 3, seg = idx & 7;       // r<128 for i=0... idx<1024: r<128
        asrc[i] = (size_t)(tile * 128 + r) * MID_DEC + seg * 4;
        adst[i] = r * PAD + seg * 4;
    }
    size_t bsrc[4]; int bdst[4];
#pragma unroll
    for (int i = 0; i < 4; i++) {
        int idx = tid + i * 512;
        int r = idx >> 3, seg = idx & 7;
        bsrc[i] = (size_t)(nc0 + r) * MID_DEC + seg * 4;
        bdst[i] = r * PAD + seg * 4;
    }
    // prefetch chunk 0
#pragma unroll
    for (int i = 0; i < 2; i++)
        CPASYNC16(sb + (uint32_t)(G2_AS0 + adst[i]) * 4, (const char*)(g_T + asrc[i]));
#pragma unroll
    for (int i = 0; i < 4; i++)
        CPASYNC16(sb + (uint32_t)(G2_BS0 + bdst[i]) * 4, (const char*)(g_W2T + bsrc[i]));
    CPCOMMIT();

    float acc[2][8][4];
#pragma unroll
    for (int mt = 0; mt < 2; mt++)
#pragma unroll
        for (int nt = 0; nt < 8; nt++)
#pragma unroll
            for (int q = 0; q < 4; q++) acc[mt][nt][q] = 0.f;

    const int arow0 = mw * 32 + (lane >> 2);
    const int brow0 = nw * 64 + (lane >> 2);
    const int kq = lane & 3;
    const uint32_t* smu = (const uint32_t*)sm;

    for (int kt = 0; kt < 24; kt++) {
        const int buf = kt & 1;
        if (kt + 1 < 24) {
            const int nb = (kt + 1) & 1;
#pragma unroll
            for (int i = 0; i < 2; i++)
                CPASYNC16(sb + (uint32_t)((nb ? G2_AS1 : G2_AS0) + adst[i]) * 4,
                          (const char*)(g_T + asrc[i] + (kt + 1) * 32));
#pragma unroll
            for (int i = 0; i < 4; i++)
                CPASYNC16(sb + (uint32_t)((nb ? G2_BS1 : G2_BS0) + bdst[i]) * 4,
                          (const char*)(g_W2T + bsrc[i] + (kt + 1) * 32));
            CPCOMMIT();
            CPWAIT1();
        } else {
            CPWAIT0();
        }
        __syncthreads();

        const int ab = buf ? G2_AS1 : G2_AS0;
        const int bb = buf ? G2_BS1 : G2_BS0;
#pragma unroll
        for (int ks = 0; ks < 4; ks++) {
            const int kb = ks * 8;
            uint32_t af[2][4];
#pragma unroll
            for (int mt = 0; mt < 2; mt++) {
                int ro = ab + (arow0 + mt * 16) * PAD + kb + kq;
                af[mt][0] = smu[ro];
                af[mt][1] = smu[ro + 8 * PAD];
                af[mt][2] = smu[ro + 4];
                af[mt][3] = smu[ro + 8 * PAD + 4];
            }
#pragma unroll
            for (int nt = 0; nt < 8; nt++) {
                uint32_t bf[2];
                int bo = bb + (brow0 + nt * 8) * PAD + kb + kq;
                bf[0] = smu[bo];
                bf[1] = smu[bo + 4];
                mma_tf32(acc[0][nt], af[0], bf);
                mma_tf32(acc[1][nt], af[1], bf);
            }
        }
        __syncthreads();
    }

    // epilogue: +b2, scatter via rowmap
    const int col00 = nc0 + nw * 64 + 2 * (lane & 3);
    const int mrow0 = mw * 32 + (lane >> 2);
#pragma unroll
    for (int mt = 0; mt < 2; mt++) {
        int r0 = mrow0 + mt * 16;
        int rm0 = rm_s[r0];
        int rm1 = rm_s[r0 + 8];
#pragma unroll
        for (int nt = 0; nt < 8; nt++) {
            int col = col00 + nt * 8;
            float2 bb = *(const float2*)(b2 + col);
            if (rm0 >= 0) {
                float2 v; v.x = acc[mt][nt][0] + bb.x; v.y = acc[mt][nt][1] + bb.y;
                *(float2*)(out + (size_t)rm0 * DDIM + col) = v;
            }
            if (rm1 >= 0) {
                float2 v; v.x = acc[mt][nt][2] + bb.x; v.y = acc[mt][nt][3] + bb.y;
                *(float2*)(out + (size_t)rm1 * DDIM + col) = v;
            }
        }
    }
}

extern "C" void kernel_launch(void* const* d_in, const int* in_sizes, int n_in,
                              void* d_out, int out_size)
{
    const float* z      = (const float*)d_in[0];
    const float* key    = (const float*)d_in[1];
    const float* sp_w1  = (const float*)d_in[2];
    const float* sp_b1  = (const float*)d_in[3];
    const float* sp_g   = (const float*)d_in[4];
    const float* sp_bt  = (const float*)d_in[5];
    const float* sp_w2  = (const float*)d_in[6];
    const float* sp_b2  = (const float*)d_in[7];
    const float* cd_w1  = (const float*)d_in[8];
    const float* cd_b1  = (const float*)d_in[9];
    const float* cd_w2  = (const float*)d_in[10];
    const float* cd_b2  = (const float*)d_in[11];
    const float* dec_w1 = (const float*)d_in[12];
    const float* dec_b1 = (const float*)d_in[13];
    const float* dec_w2 = (const float*)d_in[14];
    const float* dec_b2 = (const float*)d_in[15];
    float* out = (float*)d_out;

    const int g1_smem = G1_FLTS * 4;
    const int g2_smem = G2_FLTS * 4;
    cudaFuncSetAttribute(gemm1_kernel, cudaFuncAttributeMaxDynamicSharedMemorySize, g1_smem);
    cudaFuncSetAttribute(gemm2_kernel, cudaFuncAttributeMaxDynamicSharedMemorySize, g2_smem);

    size_pred_kernel<<<B_SZ / 8, 256>>>(z, sp_w1, sp_b1, sp_g, sp_bt, sp_w2, sp_b2);
    enc_kernel<<<65, 256>>>(cd_w1, cd_b1, cd_w2, cd_b2);
    zc_kernel<<<(B_SZ * HDIM) / 256, 256>>>(z);
    dim3 tb(32, 8);
    transpose_tf32<<<dim3(MID_DEC / 32, HDIM / 32), tb>>>(dec_w1, HDIM, MID_DEC, 0);
    transpose_tf32<<<dim3(DDIM / 32, MID_DEC / 32), tb>>>(dec_w2, MID_DEC, DDIM, 1);
    scan_kernel<<<1, 1024>>>();
    rminit_kernel<<<NROWS / 256, 256>>>();
    rmfill_kernel<<<B_SZ, MAXN>>>();

    gemm1_kernel<<<dim3(NROWS / 128, 3), 512, g1_smem>>>(key, dec_b1);
    gemm2_kernel<<<dim3(NROWS / 128, 2), 512, g2_smem>>>(dec_b2, out);

    long long x_elems = (long long)B_SZ * MAXN * DDIM;
    float* outb = ((long long)out_size >= x_elems + (long long)NROWS) ? (out + x_elems) : (float*)0;
    outfill_kernel<<<NROWS, 128>>>(out, outb);
}

// round 5
// speedup vs baseline: 6.4636x; 1.4814x over previous
#include <cuda_runtime.h>
#include <cuda_fp16.h>
#include <math.h>
#include <stdint.h>

#define B_SZ 2048
#define HDIM 1024
#define DDIM 512
#define MAXN 64
#define MID_SP 512
#define MID_CD 512
#define MID_DEC 768
#define NROWS (B_SZ * MAXN)

__device__ int    g_n[B_SZ];
__device__ int    g_off[B_SZ];
__device__ int    g_vpad;
__device__ int    g_rowmap[NROWS];
__device__ float  g_enc[65 * HDIM];
__device__ float  g_zc[B_SZ * HDIM];
__device__ __half g_W1Th[MID_DEC * HDIM];            // [768][1024]
__device__ __half g_W2Th[DDIM * MID_DEC];            // [512][768]
__device__ __half g_Th[(size_t)NROWS * MID_DEC];     // fp16 intermediate

__device__ __forceinline__ float mishf(float x) {
    float sp = log1pf(expf(x));
    if (x > 20.f) sp = x;
    return x * tanhf(sp);
}
// FMA-only mish (no MUFU): exp = 2^n * poly6, rcp = magic + 3 Newton.
__device__ __forceinline__ float mish_poly(float x) {
    float xc = fminf(fmaxf(x, -30.f), 20.f);
    float t = xc * 1.44269504089f;
    float fn = rintf(t);
    float g = (t - fn) * 0.69314718056f;
    float p = 1.f / 720.f;
    p = fmaf(p, g, 1.f / 120.f);
    p = fmaf(p, g, 1.f / 24.f);
    p = fmaf(p, g, 1.f / 6.f);
    p = fmaf(p, g, 0.5f);
    p = fmaf(p, g, 1.f);
    p = fmaf(p, g, 1.f);
    float ex = p * __uint_as_float(((unsigned)((int)fn + 127)) << 23);
    float u = 1.f + ex;
    float d = fmaf(u, u, 1.f);
    float r = __uint_as_float(0x7EF311C3u - __float_as_uint(d));
    r = r * (2.f - d * r);
    r = r * (2.f - d * r);
    r = r * (2.f - d * r);
    float m = x * (fmaf(u, u, -1.f) * r);
    return (x > 20.f) ? x : m;
}
__device__ __forceinline__ void mma_f16(float* d, const uint32_t* a, const uint32_t* b) {
    asm volatile(
        "mma.sync.aligned.m16n8k16.row.col.f32.f16.f16.f32 "
        "{%0,%1,%2,%3}, {%4,%5,%6,%7}, {%8,%9}, {%0,%1,%2,%3};"
        : "+f"(d[0]), "+f"(d[1]), "+f"(d[2]), "+f"(d[3])
        : "r"(a[0]), "r"(a[1]), "r"(a[2]), "r"(a[3]), "r"(b[0]), "r"(b[1]));
}
#define CPASYNC16(dst, src) \
    asm volatile("cp.async.cg.shared.global [%0], [%1], 16;" :: "r"(dst), "l"(src))
#define CPCOMMIT() asm volatile("cp.async.commit_group;" ::: "memory")
#define CPWAIT0()  asm volatile("cp.async.wait_group 0;" ::: "memory")
#define CPWAIT1()  asm volatile("cp.async.wait_group 1;" ::: "memory")

__device__ __forceinline__ uint32_t smem_u32(const void* p) {
    uint32_t a;
    asm("{ .reg .u64 t; cvta.to.shared.u64 t, %1; cvt.u32.u64 %0, t; }" : "=r"(a) : "l"(p));
    return a;
}
__device__ __forceinline__ uint32_t h2u(__half2 h) { return *(uint32_t*)&h; }

// ---------------- size_pred (fp32 — n must round exactly) ----------------
__global__ __launch_bounds__(256)
void size_pred_kernel(const float* __restrict__ z, const float* __restrict__ w1,
                      const float* __restrict__ b1v, const float* __restrict__ g,
                      const float* __restrict__ beta, const float* __restrict__ w2,
                      const float* __restrict__ b2v)
{
    __shared__ float z_s[8][HDIM];
    __shared__ float red1[256], red2[256];
    __shared__ float mu_s[8], rs_s[8];
    const int tid = threadIdx.x, b0 = blockIdx.x * 8;
    for (int i = tid; i < 8 * HDIM; i += 256)
        z_s[i >> 10][i & 1023] = z[(size_t)b0 * HDIM + i];
    __syncthreads();
    float pre[8][2];
#pragma unroll
    for (int r = 0; r < 8; r++) { pre[r][0] = 0.f; pre[r][1] = 0.f; }
    for (int k = 0; k < HDIM; k++) {
        float wa = w1[k * MID_SP + tid], wb = w1[k * MID_SP + tid + 256];
#pragma unroll
        for (int r = 0; r < 8; r++) {
            float zv = z_s[r][k];
            pre[r][0] = fmaf(zv, wa, pre[r][0]);
            pre[r][1] = fmaf(zv, wb, pre[r][1]);
        }
    }
    float ba = b1v[tid], bb = b1v[tid + 256];
#pragma unroll
    for (int r = 0; r < 8; r++) { pre[r][0] += ba; pre[r][1] += bb; }
    for (int r = 0; r < 8; r++) {
        red1[tid] = pre[r][0] + pre[r][1];
        red2[tid] = pre[r][0] * pre[r][0] + pre[r][1] * pre[r][1];
        __syncthreads();
        for (int s = 128; s > 0; s >>= 1) {
            if (tid < s) { red1[tid] += red1[tid + s]; red2[tid] += red2[tid + s]; }
            __syncthreads();
        }
        if (tid == 0) {
            float mu = red1[0] * (1.f / 512.f);
            float var = red2[0] * (1.f / 512.f) - mu * mu;
            mu_s[r] = mu; rs_s[r] = rsqrtf(var + 1e-5f);
        }
        __syncthreads();
    }
    float ga = g[tid], gb = g[tid + 256], bta = beta[tid], btb = beta[tid + 256];
    float w2a = w2[tid], w2b = w2[tid + 256];
    for (int r = 0; r < 8; r++) {
        float h0 = mishf((pre[r][0] - mu_s[r]) * rs_s[r] * ga + bta);
        float h1 = mishf((pre[r][1] - mu_s[r]) * rs_s[r] * gb + btb);
        red1[tid] = h0 * w2a + h1 * w2b;
        __syncthreads();
        for (int s = 128; s > 0; s >>= 1) {
            if (tid < s) red1[tid] += red1[tid + s];
            __syncthreads();
        }
        if (tid == 0) {
            int n = (int)rintf(red1[0] + b2v[0]);
            g_n[b0 + r] = min(max(n, 0), MAXN);
        }
        __syncthreads();
    }
}

// ---------------- cardinality table ----------------
__global__ __launch_bounds__(256)
void enc_kernel(const float* __restrict__ cw1, const float* __restrict__ cb1,
                const float* __restrict__ cw2, const float* __restrict__ cb2)
{
    __shared__ float m_s[MID_CD];
    const int v = blockIdx.x, tid = threadIdx.x;
    for (int j = tid; j < MID_CD; j += 256)
        m_s[j] = mishf((float)v * cw1[j] + cb1[j]);
    __syncthreads();
    for (int j = tid; j < HDIM; j += 256) {
        float acc = cb2[j];
        for (int m = 0; m < MID_CD; m++)
            acc = fmaf(m_s[m], cw2[m * HDIM + j], acc);
        g_enc[v * HDIM + j] = acc;
    }
}

__global__ __launch_bounds__(256)
void zc_kernel(const float* __restrict__ z)
{
    int idx = blockIdx.x * 256 + threadIdx.x;
    int b = idx >> 10, i = idx & 1023;
    g_zc[idx] = z[idx] - g_enc[g_n[b] * HDIM + i];
}

// transpose + fp16 convert: src[R][C] -> dst[C][R] half; which: 0->W1Th, 1->W2Th
__global__ void transpose_h(const float* __restrict__ src, int R, int C, int which)
{
    __shared__ float t[32][33];
    __half* dst = which ? g_W2Th : g_W1Th;
    int c0 = blockIdx.x * 32, r0 = blockIdx.y * 32;
#pragma unroll
    for (int i = 0; i < 32; i += 8)
        t[threadIdx.y + i][threadIdx.x] = src[(size_t)(r0 + threadIdx.y + i) * C + c0 + threadIdx.x];
    __syncthreads();
#pragma unroll
    for (int i = 0; i < 32; i += 8)
        dst[(size_t)(c0 + threadIdx.y + i) * R + r0 + threadIdx.x] = __float2half(t[threadIdx.x][threadIdx.y + i]);
}

__global__ __launch_bounds__(1024)
void scan_kernel()
{
    __shared__ int s[2048];
    int t = threadIdx.x;
    s[t] = g_n[t]; s[t + 1024] = g_n[t + 1024];
    __syncthreads();
    for (int off = 1; off < 2048; off <<= 1) {
        int a = (t >= off) ? s[t - off] : 0;
        int b = s[t + 1024 - off];
        __syncthreads();
        s[t] += a; s[t + 1024] += b;
        __syncthreads();
    }
    g_off[t] = s[t] - g_n[t];
    g_off[t + 1024] = s[t + 1024] - g_n[t + 1024];
    if (t == 1023) g_vpad = (s[2047] + 127) & ~127;
}

__global__ void rminit_kernel() { g_rowmap[blockIdx.x * 256 + threadIdx.x] = -1; }
__global__ void rmfill_kernel() {
    int b = blockIdx.x, k = threadIdx.x;
    if (k < g_n[b]) g_rowmap[g_off[b] + k] = (b << 6) | k;
}

__global__ __launch_bounds__(128)
void outfill_kernel(float* __restrict__ out, float* __restrict__ outb)
{
    int r = blockIdx.x;
    int b = r >> 6, k = r & 63;
    int n = g_n[b];
    if (outb && threadIdx.x == 0) outb[r] = (k < n) ? (float)b : -1.0f;
    if (k >= n)
        ((float4*)(out + (size_t)r * DDIM))[threadIdx.x] = make_float4(0.f, 0.f, 0.f, 0.f);
}

// =====================================================================
// GEMM1 (fp16 HMMA): g_Th = half(mish( (zc*key) @ W1 + b1 ))
// CTA 128m x 256n, 512 thr, K=1024, chunk 32 halves, row stride 80B (20 words)
// smem bytes: rm 0..512 | A 512..10752 | B0 10752..31232 | B1 31232..51712
// =====================================================================
#define G1_AW   128
#define G1_B0W  2688
#define G1_B1W  7808
#define G1_B0B  10752u
#define G1_B1B  31232u
#define G1_BYTES 51712

__global__ void __launch_bounds__(512, 1)
gemm1_kernel(const float* __restrict__ key, const float* __restrict__ b1)
{
    const int tile = blockIdx.x;
    if (tile * 128 >= g_vpad) return;
    extern __shared__ uint32_t smw[];
    int* rm_s = (int*)smw;
    char* smb = (char*)smw;
    const uint32_t sb = smem_u32(smw);

    const int tid = threadIdx.x, lane = tid & 31, wid = tid >> 5;
    const int mw = wid & 3, nw = wid >> 2;
    const int nc0 = blockIdx.y * 256;

    if (tid < 128) rm_s[tid] = g_rowmap[tile * 128 + tid];
    __syncthreads();

    // A source map: 2 x (row, seg of 4 floats)
    const float* zp[2]; const float* kp[2]; uint32_t adst[2];
#pragma unroll
    for (int i = 0; i < 2; i++) {
        int idx = tid + i * 512;
        int r = idx >> 3, seg = idx & 7;
        int rm = rm_s[r]; if (rm < 0) rm = 0;
        zp[i] = g_zc + (size_t)(rm >> 6) * HDIM + seg * 4;
        kp[i] = key + (size_t)(rm & 63) * HDIM + seg * 4;
        adst[i] = 512u + (uint32_t)r * 80u + (uint32_t)seg * 8u;
    }
    // B source map: 2 x (row, seg of 8 halves)
    const __half* bsrc[2]; uint32_t boff[2];
#pragma unroll
    for (int i = 0; i < 2; i++) {
        int idx = tid + i * 512;
        int r = idx >> 2, seg = idx & 3;
        bsrc[i] = g_W1Th + (size_t)(nc0 + r) * HDIM + seg * 8;
        boff[i] = (uint32_t)r * 80u + (uint32_t)seg * 16u;
    }

    float4 za[2], ka[2];
#pragma unroll
    for (int i = 0; i < 2; i++) { za[i] = *(const float4*)zp[i]; ka[i] = *(const float4*)kp[i]; }
#pragma unroll
    for (int i = 0; i < 2; i++)
        CPASYNC16(sb + G1_B0B + boff[i], (const char*)bsrc[i]);
    CPCOMMIT();

    float acc[2][8][4];
#pragma unroll
    for (int mt = 0; mt < 2; mt++)
#pragma unroll
        for (int nt = 0; nt < 8; nt++)
#pragma unroll
            for (int q = 0; q < 4; q++) acc[mt][nt][q] = 0.f;

    const int arow0 = mw * 32 + (lane >> 2);
    const int brow0 = nw * 64 + (lane >> 2);
    const int kq = lane & 3;

    for (int kt = 0; kt < 32; kt++) {
        const int buf = kt & 1;
#pragma unroll
        for (int i = 0; i < 2; i++) {
            float4 p;
            p.x = za[i].x * ka[i].x; p.y = za[i].y * ka[i].y;
            p.z = za[i].z * ka[i].z; p.w = za[i].w * ka[i].w;
            uint2 v;
            v.x = h2u(__floats2half2_rn(p.x, p.y));
            v.y = h2u(__floats2half2_rn(p.z, p.w));
            *(uint2*)(smb + adst[i]) = v;
        }
        if (kt + 1 < 32) {
#pragma unroll
            for (int i = 0; i < 2; i++) {
                za[i] = *(const float4*)(zp[i] + (kt + 1) * 32);
                ka[i] = *(const float4*)(kp[i] + (kt + 1) * 32);
            }
            const uint32_t bb = ((kt + 1) & 1) ? G1_B1B : G1_B0B;
#pragma unroll
            for (int i = 0; i < 2; i++)
                CPASYNC16(sb + bb + boff[i], (const char*)(bsrc[i] + (kt + 1) * 32));
            CPCOMMIT();
            CPWAIT1();
        } else {
            CPWAIT0();
        }
        __syncthreads();

        const uint32_t bw = buf ? G1_B1W : G1_B0W;
#pragma unroll
        for (int ks = 0; ks < 2; ks++) {
            const int kb = ks * 8;
            uint32_t af[2][4];
#pragma unroll
            for (int mt = 0; mt < 2; mt++) {
                int ro = G1_AW + (arow0 + mt * 16) * 20 + kb + kq;
                af[mt][0] = smw[ro];
                af[mt][1] = smw[ro + 160];
                af[mt][2] = smw[ro + 4];
                af[mt][3] = smw[ro + 164];
            }
#pragma unroll
            for (int nt = 0; nt < 8; nt++) {
                uint32_t bf[2];
                int bo = bw + (brow0 + nt * 8) * 20 + kb + kq;
                bf[0] = smw[bo];
                bf[1] = smw[bo + 4];
                mma_f16(acc[0][nt], af[0], bf);
                mma_f16(acc[1][nt], af[1], bf);
            }
        }
        __syncthreads();
    }

    // epilogue: +bias, mish, half -> g_Th
    const int col00 = nc0 + nw * 64 + 2 * (lane & 3);
    const int row00 = tile * 128 + mw * 32 + (lane >> 2);
#pragma unroll
    for (int mt = 0; mt < 2; mt++) {
#pragma unroll
        for (int nt = 0; nt < 8; nt++) {
            int col = col00 + nt * 8;
            float2 bb = *(const float2*)(b1 + col);
            __half2 v0 = __floats2half2_rn(mish_poly(acc[mt][nt][0] + bb.x),
                                           mish_poly(acc[mt][nt][1] + bb.y));
            __half2 v1 = __floats2half2_rn(mish_poly(acc[mt][nt][2] + bb.x),
                                           mish_poly(acc[mt][nt][3] + bb.y));
            *(__half2*)(g_Th + (size_t)(row00 + mt * 16) * MID_DEC + col) = v0;
            *(__half2*)(g_Th + (size_t)(row00 + mt * 16 + 8) * MID_DEC + col) = v1;
        }
    }
}

// =====================================================================
// GEMM2 (fp16 HMMA): out = g_Th @ W2 + b2, scatter by rowmap
// smem bytes: rm 0..512 | A0 512..10752 | A1 10752..20992 | B0 20992..41472 | B1 41472..61952
// =====================================================================
#define G2_A0W  128
#define G2_A1W  2688
#define G2_B0W  5248
#define G2_B1W  10368
#define G2_A0B  512u
#define G2_A1B  10752u
#define G2_B0B  20992u
#define G2_B1B  41472u
#define G2_BYTES 61952

__global__ void __launch_bounds__(512, 1)
gemm2_kernel(const float* __restrict__ b2, float* __restrict__ out)
{
    const int tile = blockIdx.x;
    if (tile * 128 >= g_vpad) return;
    extern __shared__ uint32_t smw[];
    int* rm_s = (int*)smw;
    const uint32_t sb = smem_u32(smw);

    const int tid = threadIdx.x, lane = tid & 31, wid = tid >> 5;
    const int mw = wid & 3, nw = wid >> 2;
    const int nc0 = blockIdx.y * 256;

    if (tid < 128) rm_s[tid] = g_rowmap[tile * 128 + tid];

    // A: 1 x 16B per thread; B: 2 x 16B per thread
    const __half* asrc = g_Th + (size_t)(tile * 128 + (tid >> 2)) * MID_DEC + (tid & 3) * 8;
    const uint32_t aoff = (uint32_t)(tid >> 2) * 80u + (uint32_t)(tid & 3) * 16u;
    const __half* bsrc[2]; uint32_t boff[2];
#pragma unroll
    for (int i = 0; i < 2; i++) {
        int idx = tid + i * 512;
        int r = idx >> 2, seg = idx & 3;
        bsrc[i] = g_W2Th + (size_t)(nc0 + r) * MID_DEC + seg * 8;
        boff[i] = (uint32_t)r * 80u + (uint32_t)seg * 16u;
    }

    CPASYNC16(sb + G2_A0B + aoff, (const char*)asrc);
#pragma unroll
    for (int i = 0; i < 2; i++)
        CPASYNC16(sb + G2_B0B + boff[i], (const char*)bsrc[i]);
    CPCOMMIT();

    float acc[2][8][4];
#pragma unroll
    for (int mt = 0; mt < 2; mt++)
#pragma unroll
        for (int nt = 0; nt < 8; nt++)
#pragma unroll
            for (int q = 0; q < 4; q++) acc[mt][nt][q] = 0.f;

    const int arow0 = mw * 32 + (lane >> 2);
    const int brow0 = nw * 64 + (lane >> 2);
    const int kq = lane & 3;

    for (int kt = 0; kt < 24; kt++) {
        const int buf = kt & 1;
        if (kt + 1 < 24) {
            const int nb = (kt + 1) & 1;
            CPASYNC16(sb + (nb ? G2_A1B : G2_A0B) + aoff, (const char*)(asrc + (kt + 1) * 32));
#pragma unroll
            for (int i = 0; i < 2; i++)
                CPASYNC16(sb + (nb ? G2_B1B : G2_B0B) + boff[i], (const char*)(bsrc[i] + (kt + 1) * 32));
            CPCOMMIT();
            CPWAIT1();
        } else {
            CPWAIT0();
        }
        __syncthreads();

        const uint32_t aw = buf ? G2_A1W : G2_A0W;
        const uint32_t bw = buf ? G2_B1W : G2_B0W;
#pragma unroll
        for (int ks = 0; ks < 2; ks++) {
            const int kb = ks * 8;
            uint32_t af[2][4];
#pragma unroll
            for (int mt = 0; mt < 2; mt++) {
                int ro = aw + (arow0 + mt * 16) * 20 + kb + kq;
                af[mt][0] = smw[ro];
                af[mt][1] = smw[ro + 160];
                af[mt][2] = smw[ro + 4];
                af[mt][3] = smw[ro + 164];
            }
#pragma unroll
            for (int nt = 0; nt < 8; nt++) {
                uint32_t bf[2];
                int bo = bw + (brow0 + nt * 8) * 20 + kb + kq;
                bf[0] = smw[bo];
                bf[1] = smw[bo + 4];
                mma_f16(acc[0][nt], af[0], bf);
                mma_f16(acc[1][nt], af[1], bf);
            }
        }
        __syncthreads();
    }

    // epilogue: +b2, scatter via rowmap
    const int col00 = nc0 + nw * 64 + 2 * (lane & 3);
    const int mrow0 = mw * 32 + (lane >> 2);
#pragma unroll
    for (int mt = 0; mt < 2; mt++) {
        int r0 = mrow0 + mt * 16;
        int rm0 = rm_s[r0];
        int rm1 = rm_s[r0 + 8];
#pragma unroll
        for (int nt = 0; nt < 8; nt++) {
            int col = col00 + nt * 8;
            float2 bb = *(const float2*)(b2 + col);
            if (rm0 >= 0) {
                float2 v; v.x = acc[mt][nt][0] + bb.x; v.y = acc[mt][nt][1] + bb.y;
                *(float2*)(out + (size_t)rm0 * DDIM + col) = v;
            }
            if (rm1 >= 0) {
                float2 v; v.x = acc[mt][nt][2] + bb.x; v.y = acc[mt][nt][3] + bb.y;
                *(float2*)(out + (size_t)rm1 * DDIM + col) = v;
            }
        }
    }
}

extern "C" void kernel_launch(void* const* d_in, const int* in_sizes, int n_in,
                              void* d_out, int out_size)
{
    const float* z      = (const float*)d_in[0];
    const float* key    = (const float*)d_in[1];
    const float* sp_w1  = (const float*)d_in[2];
    const float* sp_b1  = (const float*)d_in[3];
    const float* sp_g   = (const float*)d_in[4];
    const float* sp_bt  = (const float*)d_in[5];
    const float* sp_w2  = (const float*)d_in[6];
    const float* sp_b2  = (const float*)d_in[7];
    const float* cd_w1  = (const float*)d_in[8];
    const float* cd_b1  = (const float*)d_in[9];
    const float* cd_w2  = (const float*)d_in[10];
    const float* cd_b2  = (const float*)d_in[11];
    const float* dec_w1 = (const float*)d_in[12];
    const float* dec_b1 = (const float*)d_in[13];
    const float* dec_w2 = (const float*)d_in[14];
    const float* dec_b2 = (const float*)d_in[15];
    float* out = (float*)d_out;

    cudaFuncSetAttribute(gemm1_kernel, cudaFuncAttributeMaxDynamicSharedMemorySize, G1_BYTES);
    cudaFuncSetAttribute(gemm2_kernel, cudaFuncAttributeMaxDynamicSharedMemorySize, G2_BYTES);

    size_pred_kernel<<<B_SZ / 8, 256>>>(z, sp_w1, sp_b1, sp_g, sp_bt, sp_w2, sp_b2);
    enc_kernel<<<65, 256>>>(cd_w1, cd_b1, cd_w2, cd_b2);
    zc_kernel<<<(B_SZ * HDIM) / 256, 256>>>(z);
    dim3 tb(32, 8);
    transpose_h<<<dim3(MID_DEC / 32, HDIM / 32), tb>>>(dec_w1, HDIM, MID_DEC, 0);
    transpose_h<<<dim3(DDIM / 32, MID_DEC / 32), tb>>>(dec_w2, MID_DEC, DDIM, 1);
    scan_kernel<<<1, 1024>>>();
    rminit_kernel<<<NROWS / 256, 256>>>();
    rmfill_kernel<<<B_SZ, MAXN>>>();

    gemm1_kernel<<<dim3(NROWS / 128, 3), 512, G1_BYTES>>>(key, dec_b1);
    gemm2_kernel<<<dim3(NROWS / 128, 2), 512, G2_BYTES>>>(dec_b2, out);

    long long x_elems = (long long)B_SZ * MAXN * DDIM;
    float* outb = ((long long)out_size >= x_elems + (long long)NROWS) ? (out + x_elems) : (float*)0;
    outfill_kernel<<<NROWS, 128>>>(out, outb);
}